// round 1
// baseline (speedup 1.0000x reference)
#include <cuda_runtime.h>

#define BATCH   4
#define NPATCH  4096
#define DIM     256
#define MAXC    5
#define INV_T   (1.0f/0.07f)
#define NEG_FILL (-10.0f)

#define TR   128              // rows per CTA tile
#define TC   128              // cols per chunk
#define NCH  (NPATCH/TC)      // 32 chunks
#define KB   16               // k per smem piece
#define NKB  (DIM/KB)         // 16 pieces
#define BSTR 132              // Bs row stride in floats (padded)
#define PIECE (KB*BSTR)       // floats per Bs buffer

#define SMEM_FLOATS (DIM*TR + 2*PIECE + TC)
#define SMEM_BYTES  (SMEM_FLOATS*4)

__device__ float g_pos[BATCH*NPATCH];
__device__ float g_rowmin[BATCH*NPATCH];
__device__ float g_lseneg[BATCH*NPATCH];

__device__ __forceinline__ unsigned fenc(float f) {
    unsigned u = __float_as_uint(f);
    return (u & 0x80000000u) ? ~u : (u | 0x80000000u);
}
__device__ __forceinline__ float fdec(unsigned e) {
    return __uint_as_float((e & 0x80000000u) ? (e & 0x7FFFFFFFu) : ~e);
}

// ---------------------------------------------------------------------------
// Kernel 1: fused NT-GEMM + class-masked row reductions.
// grid = (NPATCH/TR, BATCH), block = 256 threads (16x16), 8x8 microtile.
// Per row n (within batch): row_min (raw logits, different-class cols),
// lse_neg = logsumexp(logits/T over different-class cols), pos = diag/T.
// ---------------------------------------------------------------------------
__global__ __launch_bounds__(256, 1)
void nce_main_kernel(const float* __restrict__ src,
                     const float* __restrict__ tgt,
                     const int*   __restrict__ cls)
{
    extern __shared__ float smem[];
    float* As = smem;                       // [DIM][TR] transposed src tile
    float* Bs = smem + DIM*TR;              // 2 double-buffered pieces
    int*   Cc = (int*)(smem + DIM*TR + 2*PIECE);  // col classes

    const int tid = threadIdx.x;
    const int tx = tid & 15;
    const int ty = tid >> 4;
    const int bt = blockIdx.y;
    const int rt = blockIdx.x;
    const int rowBase = bt*NPATCH + rt*TR;

    // ---- load src tile transposed into smem (once per CTA) ----
    {
        const float4* s4 = (const float4*)src + (size_t)rowBase * (DIM/4);
        for (int idx = tid; idx < TR*(DIM/4); idx += 256) {
            int r  = idx >> 6;       // DIM/4 = 64
            int kq = idx & 63;
            float4 v = s4[r*64 + kq];
            As[(kq*4+0)*TR + r] = v.x;
            As[(kq*4+1)*TR + r] = v.y;
            As[(kq*4+2)*TR + r] = v.z;
            As[(kq*4+3)*TR + r] = v.w;
        }
    }

    int clsr[8];
    #pragma unroll
    for (int i = 0; i < 8; i++) clsr[i] = cls[rowBase + ty*8 + i];

    float mrow[8], srow[8], minrow[8];
    #pragma unroll
    for (int i = 0; i < 8; i++) { mrow[i] = -1e30f; srow[i] = 0.0f; minrow[i] = 3.0e38f; }

    const float4* t4 = (const float4*)tgt + (size_t)(bt*NPATCH) * (DIM/4);

    const int i0 = tid, i1 = tid + 256;
    const int c0 = i0 >> 2, q0 = i0 & 3;
    const int c1 = i1 >> 2, q1 = i1 & 3;

    for (int ch = 0; ch < NCH; ch++) {
        const int col0 = ch*TC;
        __syncthreads();    // protect Cc/Bs from previous chunk's readers
        if (tid < TC) Cc[tid] = cls[bt*NPATCH + col0 + tid];

        // preload piece 0
        float4 pv0 = t4[(col0 + c0)*64 + q0];
        float4 pv1 = t4[(col0 + c1)*64 + q1];
        {
            float* B0 = Bs;
            B0[(q0*4+0)*BSTR + c0] = pv0.x; B0[(q0*4+1)*BSTR + c0] = pv0.y;
            B0[(q0*4+2)*BSTR + c0] = pv0.z; B0[(q0*4+3)*BSTR + c0] = pv0.w;
            B0[(q1*4+0)*BSTR + c1] = pv1.x; B0[(q1*4+1)*BSTR + c1] = pv1.y;
            B0[(q1*4+2)*BSTR + c1] = pv1.z; B0[(q1*4+3)*BSTR + c1] = pv1.w;
        }
        __syncthreads();

        float acc[8][8];
        #pragma unroll
        for (int i = 0; i < 8; i++)
            #pragma unroll
            for (int j = 0; j < 8; j++) acc[i][j] = 0.0f;

        int buf = 0;
        for (int kb = 0; kb < NKB; kb++) {
            float4 nv0, nv1;
            if (kb + 1 < NKB) {
                nv0 = t4[(col0 + c0)*64 + (kb+1)*4 + q0];
                nv1 = t4[(col0 + c1)*64 + (kb+1)*4 + q1];
            }
            const float* Bp = Bs + buf*PIECE;
            #pragma unroll
            for (int kk = 0; kk < KB; kk++) {
                const int k = kb*KB + kk;
                float4 a0 = *(const float4*)(As + k*TR + ty*8);
                float4 a1 = *(const float4*)(As + k*TR + ty*8 + 4);
                float4 b0 = *(const float4*)(Bp + kk*BSTR + tx*8);
                float4 b1 = *(const float4*)(Bp + kk*BSTR + tx*8 + 4);
                float av[8] = {a0.x,a0.y,a0.z,a0.w,a1.x,a1.y,a1.z,a1.w};
                float bv[8] = {b0.x,b0.y,b0.z,b0.w,b1.x,b1.y,b1.z,b1.w};
                #pragma unroll
                for (int i = 0; i < 8; i++)
                    #pragma unroll
                    for (int j = 0; j < 8; j++)
                        acc[i][j] = fmaf(av[i], bv[j], acc[i][j]);
            }
            if (kb + 1 < NKB) {
                float* Bn = Bs + (buf^1)*PIECE;
                Bn[(q0*4+0)*BSTR + c0] = nv0.x; Bn[(q0*4+1)*BSTR + c0] = nv0.y;
                Bn[(q0*4+2)*BSTR + c0] = nv0.z; Bn[(q0*4+3)*BSTR + c0] = nv0.w;
                Bn[(q1*4+0)*BSTR + c1] = nv1.x; Bn[(q1*4+1)*BSTR + c1] = nv1.y;
                Bn[(q1*4+2)*BSTR + c1] = nv1.z; Bn[(q1*4+3)*BSTR + c1] = nv1.w;
                __syncthreads();
                buf ^= 1;
            }
        }

        // ---- fused epilogue: masked min + online logsumexp ----
        int cc[8];
        #pragma unroll
        for (int j = 0; j < 8; j++) cc[j] = Cc[tx*8 + j];

        #pragma unroll
        for (int i = 0; i < 8; i++) {
            const int cr = clsr[i];
            float m = mrow[i], s = srow[i], mn = minrow[i];
            #pragma unroll
            for (int j = 0; j < 8; j++) {
                float v = acc[i][j];
                bool valid = (cr != cc[j]);
                mn = fminf(mn, valid ? v : 3.0e38f);
                float le = valid ? v * INV_T : -1e30f;
                float mnew = fmaxf(m, le);
                s = s * __expf(m - mnew) + __expf(le - mnew);
                m = mnew;
            }
            mrow[i] = m; srow[i] = s; minrow[i] = mn;
        }

        // diagonal tile -> positive logits
        if (ch == rt && tx == ty) {
            #pragma unroll
            for (int i = 0; i < 8; i++)
                g_pos[rowBase + ty*8 + i] = acc[i][i] * INV_T;
        }
    }

    // ---- merge across the 16 lanes sharing each row (shfl butterfly) ----
    #pragma unroll
    for (int i = 0; i < 8; i++) {
        float m = mrow[i], s = srow[i], mn = minrow[i];
        #pragma unroll
        for (int off = 1; off < 16; off <<= 1) {
            float mo = __shfl_xor_sync(0xffffffffu, m,  off, 16);
            float so = __shfl_xor_sync(0xffffffffu, s,  off, 16);
            float no = __shfl_xor_sync(0xffffffffu, mn, off, 16);
            mn = fminf(mn, no);
            float mm = fmaxf(m, mo);
            s = s * __expf(m - mm) + so * __expf(mo - mm);
            m = mm;
        }
        if (tx == 0) {
            int g = rowBase + ty*8 + i;
            g_rowmin[g] = mn;
            g_lseneg[g] = m + __logf(s);
        }
    }
}

// ---------------------------------------------------------------------------
// Kernel 2: per-batch class min/count, pad term, final loss, stable
// counting-sort reorder. grid = BATCH, block = 512 (8 consecutive rows/thread).
// ---------------------------------------------------------------------------
__global__ __launch_bounds__(512, 1)
void nce_finalize_kernel(const int* __restrict__ cls, float* __restrict__ out)
{
    __shared__ unsigned sMin[MAXC];
    __shared__ int      sCnt[MAXC];
    __shared__ int      sOff[MAXC];
    __shared__ float    sSmall[MAXC];
    __shared__ int      scanb[512];

    const int b = blockIdx.x;
    const int t = threadIdx.x;
    const int base = b*NPATCH + t*8;

    if (t < MAXC) { sMin[t] = 0xFFFFFFFFu; sCnt[t] = 0; }
    __syncthreads();

    int   myc[8];
    float lmin[MAXC];
    int   lcnt[MAXC];
    #pragma unroll
    for (int c = 0; c < MAXC; c++) { lmin[c] = 3.0e38f; lcnt[c] = 0; }

    #pragma unroll
    for (int i = 0; i < 8; i++) {
        int c = cls[base + i];
        myc[i] = c;
        float rm = g_rowmin[base + i];
        lmin[c] = fminf(lmin[c], rm);
        lcnt[c]++;
    }
    #pragma unroll
    for (int c = 0; c < MAXC; c++) {
        if (lcnt[c]) {
            atomicMin(&sMin[c], fenc(lmin[c]));
            atomicAdd(&sCnt[c], lcnt[c]);
        }
    }
    __syncthreads();

    if (t == 0) {
        int run = 0;
        for (int c = 0; c < MAXC; c++) {
            sOff[c] = run; run += sCnt[c];
            sSmall[c] = fminf(fdec(sMin[c]), NEG_FILL) * INV_T;
        }
    }

    // stable ranks: block-wide exclusive scan of per-thread class counts
    int rb[MAXC];
    for (int c = 0; c < MAXC; c++) {
        scanb[t] = lcnt[c];
        __syncthreads();
        for (int off = 1; off < 512; off <<= 1) {
            int v = (t >= off) ? scanb[t - off] : 0;
            __syncthreads();
            scanb[t] += v;
            __syncthreads();
        }
        rb[c] = scanb[t] - lcnt[c];
        __syncthreads();
    }

    #pragma unroll
    for (int i = 0; i < 8; i++) {
        int g = base + i;
        int c = myc[i];
        int r = rb[c]++;
        float ps = g_pos[g];
        float ln = g_lseneg[g];
        int np = sCnt[c] - 1;
        float pad = (np > 0) ? (__logf((float)np) + sSmall[c]) : -3.0e38f;
        float M = fmaxf(fmaxf(ps, ln), pad);
        float lse = M + __logf(__expf(ps - M) + __expf(ln - M) + __expf(pad - M));
        out[b*NPATCH + sOff[c] + r] = lse - ps;
    }
}

// ---------------------------------------------------------------------------
extern "C" void kernel_launch(void* const* d_in, const int* in_sizes, int n_in,
                              void* d_out, int out_size)
{
    const float* src = (const float*)d_in[0];
    const float* tgt = (const float*)d_in[1];
    const int*   cls = (const int*)d_in[2];
    float*       out = (float*)d_out;

    cudaFuncSetAttribute(nce_main_kernel,
                         cudaFuncAttributeMaxDynamicSharedMemorySize, SMEM_BYTES);

    dim3 grid(NPATCH/TR, BATCH);
    nce_main_kernel<<<grid, 256, SMEM_BYTES>>>(src, tgt, cls);
    nce_finalize_kernel<<<BATCH, 512>>>(cls, out);
}

// round 6
// speedup vs baseline: 2.0234x; 2.0234x over previous
#include <cuda_runtime.h>
#include <cuda_bf16.h>

#define BATCH   4
#define NPATCH  4096
#define DIM     256
#define MAXC    5
#define INV_T   (1.0f/0.07f)
#define NEG_FILL (-10.0f)

// smem layout
#define ASTR    264                 // halves per A row (528B, odd multiple of 16B)
#define APLANE  (128*ASTR*2)        // 67584 B per plane (hi, lo)
#define BSTRB   80                  // bytes per B slice row (64B data + 16B pad)
#define BPLANE  (128*BSTRB)         // 10240 B
#define STAGE_BYTES (2*BPLANE)      // 20480 (hi+lo)
#define NSTG    3
#define SM_A    0
#define SM_STG  (2*APLANE)                    // 135168
#define SM_CLS  (SM_STG + NSTG*STAGE_BYTES)   // 196608
#define SM_RED  (SM_CLS + NPATCH*4)           // 212992
#define SMEM_BYTES (SM_RED + 128*3*4)         // 214528

#define NCHUNK  32                  // column chunks of 128
#define NSLICE  (NCHUNK*8)          // 256 k32-slices total

__device__ __nv_bfloat16 g_hi[BATCH*NPATCH*DIM];
__device__ __nv_bfloat16 g_lo[BATCH*NPATCH*DIM];
__device__ float g_pos[BATCH*NPATCH];
__device__ float g_rowmin[BATCH*NPATCH];
__device__ float g_lseneg[BATCH*NPATCH];

// ---------------------------------------------------------------------------
__device__ __forceinline__ unsigned smem_u32(const void* p) {
    unsigned a;
    asm("{ .reg .u64 t; cvta.to.shared.u64 t, %1; cvt.u32.u64 %0, t; }" : "=r"(a) : "l"(p));
    return a;
}
__device__ __forceinline__ void cp16(unsigned dst, const void* src, int pred) {
    asm volatile("{\n\t.reg .pred p;\n\tsetp.ne.u32 p, %2, 0;\n\t"
                 "@p cp.async.cg.shared.global [%0], [%1], 16;\n\t}"
                 :: "r"(dst), "l"(src), "r"((unsigned)pred) : "memory");
}
#define CP_COMMIT() asm volatile("cp.async.commit_group;" ::: "memory")
#define CP_WAIT(N)  asm volatile("cp.async.wait_group %0;" :: "n"(N) : "memory")

__device__ __forceinline__ void ldsm_x4(unsigned* r, unsigned addr) {
    asm volatile("ldmatrix.sync.aligned.m8n8.x4.shared.b16 {%0,%1,%2,%3}, [%4];"
                 : "=r"(r[0]), "=r"(r[1]), "=r"(r[2]), "=r"(r[3]) : "r"(addr));
}
__device__ __forceinline__ void mma_bf16(float* d, const unsigned* a, unsigned b0, unsigned b1) {
    asm volatile("mma.sync.aligned.m16n8k16.row.col.f32.bf16.bf16.f32 "
                 "{%0,%1,%2,%3}, {%4,%5,%6,%7}, {%8,%9}, {%0,%1,%2,%3};"
                 : "+f"(d[0]), "+f"(d[1]), "+f"(d[2]), "+f"(d[3])
                 : "r"(a[0]), "r"(a[1]), "r"(a[2]), "r"(a[3]), "r"(b0), "r"(b1));
}

// split fp32 pair -> packed bf16 hi + lo
__device__ __forceinline__ unsigned split_pair(float a, float b, unsigned &lo) {
    __nv_bfloat16 ha = __float2bfloat16_rn(a);
    __nv_bfloat16 hb = __float2bfloat16_rn(b);
    __nv_bfloat16 la = __float2bfloat16_rn(a - __bfloat162float(ha));
    __nv_bfloat16 lb = __float2bfloat16_rn(b - __bfloat162float(hb));
    lo = ((unsigned)__bfloat16_as_ushort(lb) << 16) | (unsigned)__bfloat16_as_ushort(la);
    return ((unsigned)__bfloat16_as_ushort(hb) << 16) | (unsigned)__bfloat16_as_ushort(ha);
}
__device__ __forceinline__ unsigned fenc(float f) {
    unsigned u = __float_as_uint(f);
    return (u & 0x80000000u) ? ~u : (u | 0x80000000u);
}
__device__ __forceinline__ float fdec(unsigned e) {
    return __uint_as_float((e & 0x80000000u) ? (e & 0x7FFFFFFFu) : ~e);
}

// ---------------------------------------------------------------------------
// Kernel 0: split tgt fp32 -> bf16 hi/lo planes (row-major [b*n][k])
// ---------------------------------------------------------------------------
__global__ __launch_bounds__(256)
void convert_tgt_kernel(const float* __restrict__ tgt)
{
    size_t i = ((size_t)blockIdx.x * 256 + threadIdx.x) * 8;
    const float4* p = (const float4*)(tgt + i);
    float4 f0 = p[0], f1 = p[1];
    unsigned hi[4], lo[4];
    hi[0] = split_pair(f0.x, f0.y, lo[0]);
    hi[1] = split_pair(f0.z, f0.w, lo[1]);
    hi[2] = split_pair(f1.x, f1.y, lo[2]);
    hi[3] = split_pair(f1.z, f1.w, lo[3]);
    *(uint4*)((char*)g_hi + i*2) = *(uint4*)hi;
    *(uint4*)((char*)g_lo + i*2) = *(uint4*)lo;
}

// ---------------------------------------------------------------------------
// slice loader: one k32-slice (hi+lo) of a 128-col chunk, 3-stage cp.async
// ---------------------------------------------------------------------------
__device__ __forceinline__ void issue_slice(unsigned sb, int bt, int tid, int g)
{
    const int pred = (g < NSLICE) ? 1 : 0;
    const int gg = pred ? g : 0;
    const int ch = gg >> 3, s = gg & 7;
    const int stg = gg % NSTG;
    const int plane = tid >> 7;          // 0: hi, 1: lo
    const int row = tid & 127;           // chunk-local column index
    const __nv_bfloat16* base = plane ? g_lo : g_hi;
    const char* gsrc = (const char*)(base + ((size_t)(bt*NPATCH + ch*128 + row))*DIM + s*32);
    unsigned dst = sb + SM_STG + stg*STAGE_BYTES + plane*BPLANE + row*BSTRB;
    #pragma unroll
    for (int j = 0; j < 4; j++) cp16(dst + j*16, gsrc + j*16, pred);
    CP_COMMIT();
}

// epilogue per-element update (branchless, 1 MUFU)
__device__ __forceinline__ void proc_elem(float v, int cj, int cr,
                                          float &m, float &s, float &mn)
{
    bool valid = (cr != cj);
    mn = fminf(mn, valid ? v : 3.0e38f);
    float le = valid ? v * INV_T : -3.0e38f;
    float d = le - m;
    float e = __expf(0.0f - fabsf(d));
    bool gt = d > 0.0f;
    float s2 = fmaf(s, e, 1.0f);
    s = gt ? s2 : (s + e);
    m = gt ? le : m;
}
__device__ __forceinline__ void lse_merge(float &m, float &s, float mo, float so) {
    float mm = fmaxf(m, mo);
    s = s * __expf(m - mm) + so * __expf(mo - mm);
    m = mm;
}

// ---------------------------------------------------------------------------
// Kernel 1: bf16x3 mma.sync GEMM + fused masked min / online LSE epilogue.
// grid (32, 4); block 256 = 8 warps; warp grid 4(m) x 2(n); warp tile 32x64.
// ---------------------------------------------------------------------------
__global__ __launch_bounds__(256, 1)
void nce_main_kernel(const float* __restrict__ src, const int* __restrict__ cls)
{
    extern __shared__ __align__(16) char smem[];
    const unsigned sb = smem_u32(smem);
    const int tid = threadIdx.x;
    const int wid = tid >> 5;
    const int lane = tid & 31;
    const int wm = wid >> 1;             // 0..3: rows wm*32..+31
    const int wn = wid & 1;              // 0..1: cols wn*64..+63
    const int rt = blockIdx.x;
    const int bt = blockIdx.y;
    const int rowBase = bt*NPATCH + rt*128;

    // ---- col classes for the whole batch row ----
    int* Cc = (int*)(smem + SM_CLS);
    for (int i = tid; i < NPATCH; i += 256) Cc[i] = cls[bt*NPATCH + i];

    // ---- load + split A (128 x 256 fp32) into padded smem hi/lo planes ----
    {
        const int r = tid >> 1, half = tid & 1;
        const float4* ap = (const float4*)(src + (size_t)(rowBase + r)*DIM + half*128);
        char* hiB = smem + SM_A + r*(ASTR*2) + half*256;
        char* loB = hiB + APLANE;
        #pragma unroll
        for (int i = 0; i < 32; i++) {
            float4 v = ap[i];
            unsigned l0, l1;
            unsigned h0 = split_pair(v.x, v.y, l0);
            unsigned h1 = split_pair(v.z, v.w, l1);
            ((uint2*)hiB)[i] = make_uint2(h0, h1);
            ((uint2*)loB)[i] = make_uint2(l0, l1);
        }
    }

    // prefetch first 2 slices
    issue_slice(sb, bt, tid, 0);
    issue_slice(sb, bt, tid, 1);

    __syncthreads();   // A + Cc ready

    // per-thread fixed geometry
    int rowLoc[4], rowcls[4];
    #pragma unroll
    for (int mt = 0; mt < 2; mt++)
        #pragma unroll
        for (int h = 0; h < 2; h++) {
            int rl = wm*32 + mt*16 + h*8 + (lane >> 2);
            rowLoc[mt*2+h] = rl;
            rowcls[mt*2+h] = Cc[rt*128 + rl];
        }
    int colLoc[16];
    #pragma unroll
    for (int j = 0; j < 16; j++)
        colLoc[j] = wn*64 + (j >> 1)*8 + (lane & 3)*2 + (j & 1);

    float mst[4], sst[4], mnst[4];
    #pragma unroll
    for (int q = 0; q < 4; q++) { mst[q] = -1e30f; sst[q] = 0.0f; mnst[q] = 3.0e38f; }

    const unsigned aBase = sb + SM_A;

    int g = 2;
    for (int ch = 0; ch < NCHUNK; ch++) {
        float acc[2][8][4];
        #pragma unroll
        for (int mt = 0; mt < 2; mt++)
            #pragma unroll
            for (int nt = 0; nt < 8; nt++)
                #pragma unroll
                for (int q = 0; q < 4; q++) acc[mt][nt][q] = 0.0f;

        int cc[16];
        #pragma unroll
        for (int j = 0; j < 16; j++) cc[j] = Cc[ch*128 + colLoc[j]];

        for (int s = 0; s < 8; s++, g++) {
            CP_WAIT(1);
            __syncthreads();
            const int stg = (ch*8 + s) % NSTG;
            const unsigned bHi = sb + SM_STG + stg*STAGE_BYTES;
            const unsigned bLo = bHi + BPLANE;
            issue_slice(sb, bt, tid, g);

            #pragma unroll
            for (int kk = 0; kk < 2; kk++) {
                const int kg = s*2 + kk;                   // global k-step 0..15
                const unsigned aoff = kg*32 + (lane >> 4)*16;
                unsigned ahi[2][4], alo[2][4];
                #pragma unroll
                for (int mt = 0; mt < 2; mt++) {
                    unsigned arow = aBase + (wm*32 + mt*16 + (lane & 15))*(ASTR*2) + aoff;
                    ldsm_x4(ahi[mt], arow);
                    ldsm_x4(alo[mt], arow + APLANE);
                }
                unsigned bh[4][4], bl[4][4];
                #pragma unroll
                for (int np = 0; np < 4; np++) {
                    unsigned boff = (wn*64 + np*16 + (lane & 15))*BSTRB + kk*32 + (lane >> 4)*16;
                    ldsm_x4(bh[np], bHi + boff);
                    ldsm_x4(bl[np], bLo + boff);
                }
                #pragma unroll
                for (int mt = 0; mt < 2; mt++)
                    #pragma unroll
                    for (int np = 0; np < 4; np++) {
                        mma_bf16(acc[mt][np*2],   ahi[mt], bh[np][0], bh[np][2]);
                        mma_bf16(acc[mt][np*2+1], ahi[mt], bh[np][1], bh[np][3]);
                        mma_bf16(acc[mt][np*2],   alo[mt], bh[np][0], bh[np][2]);
                        mma_bf16(acc[mt][np*2+1], alo[mt], bh[np][1], bh[np][3]);
                        mma_bf16(acc[mt][np*2],   ahi[mt], bl[np][0], bl[np][2]);
                        mma_bf16(acc[mt][np*2+1], ahi[mt], bl[np][1], bl[np][3]);
                    }
            }
        }

        // ---- fused epilogue on register accumulators ----
        if (ch == rt) {       // diagonal chunk: extract positives
            #pragma unroll
            for (int st = 0; st < 4; st++) {
                #pragma unroll
                for (int j = 0; j < 16; j++)
                    if (colLoc[j] == rowLoc[st])
                        g_pos[rowBase + rowLoc[st]] =
                            acc[st>>1][j>>1][(st&1)*2 + (j&1)] * INV_T;
            }
        }
        #pragma unroll
        for (int st = 0; st < 4; st++) {
            const int mt = st >> 1, h = st & 1, cr = rowcls[st];
            float m = mst[st], s = sst[st], mn = mnst[st];
            #pragma unroll
            for (int j = 0; j < 16; j++)
                proc_elem(acc[mt][j>>1][h*2 + (j&1)], cc[j], cr, m, s, mn);
            mst[st] = m; sst[st] = s; mnst[st] = mn;
        }
    }

    // ---- reduce: 4-lane butterfly (lanes sharing a row), then wn pair ----
    #pragma unroll
    for (int st = 0; st < 4; st++) {
        float m = mst[st], s = sst[st], mn = mnst[st];
        #pragma unroll
        for (int off = 1; off < 4; off <<= 1) {
            float mo = __shfl_xor_sync(0xffffffffu, m,  off);
            float so = __shfl_xor_sync(0xffffffffu, s,  off);
            float no = __shfl_xor_sync(0xffffffffu, mn, off);
            mn = fminf(mn, no);
            lse_merge(m, s, mo, so);
        }
        mst[st] = m; sst[st] = s; mnst[st] = mn;
    }
    float* red = (float*)(smem + SM_RED);     // [128][3]
    __syncthreads();
    if (wn == 1 && (lane & 3) == 0) {
        #pragma unroll
        for (int st = 0; st < 4; st++) {
            int rl = rowLoc[st];
            red[rl*3+0] = mst[st]; red[rl*3+1] = sst[st]; red[rl*3+2] = mnst[st];
        }
    }
    __syncthreads();
    if (wn == 0 && (lane & 3) == 0) {
        #pragma unroll
        for (int st = 0; st < 4; st++) {
            int rl = rowLoc[st];
            float m = mst[st], s = sst[st], mn = mnst[st];
            mn = fminf(mn, red[rl*3+2]);
            lse_merge(m, s, red[rl*3+0], red[rl*3+1]);
            g_rowmin[rowBase + rl] = mn;
            g_lseneg[rowBase + rl] = m + __logf(s);
        }
    }
    CP_WAIT(0);
}

// ---------------------------------------------------------------------------
// Kernel 2: per-batch class min/count + final loss + stable counting-sort.
// ---------------------------------------------------------------------------
__global__ __launch_bounds__(512, 1)
void nce_finalize_kernel(const int* __restrict__ cls, float* __restrict__ out)
{
    __shared__ unsigned sMin[MAXC];
    __shared__ int      sCnt[MAXC];
    __shared__ int      sOff[MAXC];
    __shared__ float    sSmall[MAXC];
    __shared__ int      wsum[16 * MAXC];

    const int b = blockIdx.x;
    const int t = threadIdx.x;
    const int lane = t & 31;
    const int w = t >> 5;
    const int base = b*NPATCH + t*8;

    if (t < MAXC) { sMin[t] = 0xFFFFFFFFu; sCnt[t] = 0; }
    __syncthreads();

    int myc[8];
    float lmin[MAXC];
    int   lcnt[MAXC];
    #pragma unroll
    for (int c = 0; c < MAXC; c++) { lmin[c] = 3.0e38f; lcnt[c] = 0; }
    #pragma unroll
    for (int i = 0; i < 8; i++) {
        int c = cls[base + i];
        myc[i] = c;
        lmin[c] = fminf(lmin[c], g_rowmin[base + i]);
        lcnt[c]++;
    }
    #pragma unroll
    for (int c = 0; c < MAXC; c++)
        if (lcnt[c]) { atomicMin(&sMin[c], fenc(lmin[c])); atomicAdd(&sCnt[c], lcnt[c]); }
    __syncthreads();

    if (t == 0) {
        int run = 0;
        for (int c = 0; c < MAXC; c++) {
            sOff[c] = run; run += sCnt[c];
            sSmall[c] = fminf(fdec(sMin[c]), NEG_FILL) * INV_T;
        }
    }

    int excl[MAXC];
    #pragma unroll
    for (int c = 0; c < MAXC; c++) {
        int x = lcnt[c];
        #pragma unroll
        for (int off = 1; off < 32; off <<= 1) {
            int v = __shfl_up_sync(0xffffffffu, x, off);
            if (lane >= off) x += v;
        }
        excl[c] = x - lcnt[c];
        if (lane == 31) wsum[w*MAXC + c] = x;
    }
    __syncthreads();

    int rb[MAXC];
    #pragma unroll
    for (int c = 0; c < MAXC; c++) {
        int p = 0;
        for (int ww = 0; ww < 16; ww++) if (ww < w) p += wsum[ww*MAXC + c];
        rb[c] = p + excl[c];
    }

    #pragma unroll
    for (int i = 0; i < 8; i++) {
        int gidx = base + i;
        int c = myc[i];
        int r = rb[c]++;
        float ps = g_pos[gidx];
        float ln = g_lseneg[gidx];
        int np = sCnt[c] - 1;
        float pad = (np > 0) ? (__logf((float)np) + sSmall[c]) : -3.0e38f;
        float M = fmaxf(fmaxf(ps, ln), pad);
        float lse = M + __logf(__expf(ps - M) + __expf(ln - M) + __expf(pad - M));
        out[b*NPATCH + sOff[c] + r] = lse - ps;
    }
}

// ---------------------------------------------------------------------------
extern "C" void kernel_launch(void* const* d_in, const int* in_sizes, int n_in,
                              void* d_out, int out_size)
{
    const float* src = (const float*)d_in[0];
    const float* tgt = (const float*)d_in[1];
    const int*   cls = (const int*)d_in[2];
    float*       out = (float*)d_out;

    cudaFuncSetAttribute(nce_main_kernel,
                         cudaFuncAttributeMaxDynamicSharedMemorySize, SMEM_BYTES);

    convert_tgt_kernel<<<(BATCH*NPATCH*DIM)/(256*8), 256>>>(tgt);
    dim3 grid(NPATCH/128, BATCH);
    nce_main_kernel<<<grid, 256, SMEM_BYTES>>>(src, cls);
    nce_finalize_kernel<<<BATCH, 512>>>(cls, out);
}